// round 13
// baseline (speedup 1.0000x reference)
#include <cuda_runtime.h>

#define HLOG2E 0.7213475204444817f   // log2(e)/2
#define EPS    1e-8f

__device__ float        g_partials[8192];
__device__ unsigned int g_done;   // zero-init; last CTA resets -> graph-replay safe

__device__ __forceinline__ float ex2a(float x) {
    float r; asm("ex2.approx.ftz.f32 %0, %1;" : "=f"(r) : "f"(x)); return r;
}
__device__ __forceinline__ float lg2a(float x) {
    float r; asm("lg2.approx.ftz.f32 %0, %1;" : "=f"(r) : "f"(x)); return r;
}

// Pair identity: log2(sig(d)) + log2(sig(-d)) = -2*lg2(2^{d/2} + 2^{-d/2}).
// Q = e^{s/2}, R = 1/Q. Gains prescaled by 2, so the folded contribution of
// unordered pair {i,j} is  -|g2i - g2j| * lg2(Qi*Rj + Ri*Qj). One MUFU/pair.

// Block-per-row, 256 threads = two k-parity groups of 128. Group h sums
// cyclic distances k = 1+h, 3+h, ... (serial path halved). Row staged as
// s_QR (Q,R) + s_g2 (2*gain) by group 0, first 64 entries mirrored past L
// so partner index i+k never wraps.
__global__ void __launch_bounds__(256) ndcg_kernel(
    const float* __restrict__ scores,
    const int*   __restrict__ relev,
    const int*   __restrict__ qlen,
    float*       __restrict__ out,
    int D, int B)
{
    const int tid = threadIdx.x;
    const int b   = blockIdx.x;
    const int i   = tid & 127;          // doc index
    const int h   = tid >> 7;           // k-parity group

    __shared__ float2 s_QR[192];
    __shared__ float  s_g2[192];
    __shared__ int    s_cnt[8];
    __shared__ float  s_rn[8], s_ri[8];
    __shared__ int    s_last;

    const int  L     = qlen[b];
    const bool valid = (i < L);

    // both groups load and compute their own Q,R,g2 (same addresses, L1-hot)
    const float sc = scores[b * D + i];
    const int   rv = relev[b * D + i];
    const float Q  = ex2a(sc * HLOG2E);       // e^{s/2}
    const float R  = ex2a(sc * (-HLOG2E));    // e^{-s/2}
    const float g2 = valid ? (float)(2 * ((1 << rv) - 1)) : 0.0f;

    if (h == 0) {
        const float2 qr = make_float2(Q, R);
        if (i < 8) s_cnt[i] = 0;
        if (valid)  { s_QR[i] = qr;     s_g2[i] = g2; }     // primary
        if (i < 64) { s_QR[L + i] = qr; s_g2[L + i] = g2; } // mirror [L,L+63]
    }
    __syncthreads();
    if (h == 0 && valid) atomicAdd(&s_cnt[rv], 1);
    __syncthreads();

    // ---- this group's share of the pairwise sum (2 chains, stride-2 k) ----
    float num = 0.0f;
    if (valid && L > 1) {
        const int     halfm = (L - 1) >> 1;
        const float2* bq = &s_QR[i];
        const float*  bg = &s_g2[i];
        float n0 = 0.0f, n1 = 0.0f;

        int k = 1 + h;
        for (; k + 2 <= halfm; k += 4) {
            const float2 p0 = bq[k];
            const float2 p1 = bq[k + 2];
            const float  v0 = fmaf(Q, p0.y, R * p0.x);   // Qi*Rj + Ri*Qj
            const float  v1 = fmaf(Q, p1.y, R * p1.x);
            const float  l0 = lg2a(v0);                  // MUFU.LG2
            const float  l1 = lg2a(v1);
            const float  d0 = g2 - bg[k];
            const float  d1 = g2 - bg[k + 2];
            n0 = fmaf(-fabsf(d0), l0, n0);
            n1 = fmaf(-fabsf(d1), l1, n1);
        }
        if (k <= halfm) {
            const float2 p0 = bq[k];
            const float  v0 = fmaf(Q, p0.y, R * p0.x);
            n0 = fmaf(-fabsf(g2 - bg[k]), lg2a(v0), n0);
        }
        // tie distance k=L/2 (L even): counted once, by group 1, i < L/2
        if ((h == 1) && ((L & 1) == 0) && (i < (L >> 1))) {
            const int    m  = L >> 1;
            const float2 p0 = s_QR[i + m];
            const float  v0 = fmaf(Q, p0.y, R * p0.x);
            n1 = fmaf(-fabsf(g2 - s_g2[i + m]), lg2a(v0), n1);
        }
        num = n0 + n1;
    }

    // ---- ideal DCG via counting sort (group 0 only; gains in {0,1,3,7,15}) ----
    float idl = 0.0f;
    if (h == 0 && valid) {
        const int c4 = s_cnt[4];
        const int c3 = c4 + s_cnt[3];
        const int c2 = c3 + s_cnt[2];
        const int c1 = c2 + s_cnt[1];
        float gr;
        if      (i < c4) gr = 15.0f;
        else if (i < c3) gr = 7.0f;
        else if (i < c2) gr = 3.0f;
        else if (i < c1) gr = 1.0f;
        else             gr = 0.0f;
        idl = __fdividef(gr, lg2a((float)(i + 2)));
    }

    // ---- block reduction of (num, idl) across 8 warps ----
    #pragma unroll
    for (int off = 16; off > 0; off >>= 1) {
        num += __shfl_down_sync(0xFFFFFFFFu, num, off);
        idl += __shfl_down_sync(0xFFFFFFFFu, idl, off);
    }
    const int wid  = tid >> 5;
    const int lane = tid & 31;
    if (lane == 0) { s_rn[wid] = num; s_ri[wid] = idl; }
    __syncthreads();
    if (tid == 0) {
        float n = 0.0f, id = 0.0f;
        #pragma unroll
        for (int w = 0; w < 8; ++w) { n += s_rn[w]; id += s_ri[w]; }
        g_partials[b] = -n / (id + EPS);
        __threadfence();
        const unsigned int t = atomicAdd(&g_done, 1u);
        s_last = (t == (unsigned int)(gridDim.x - 1));
    }
    __syncthreads();

    // ---- last CTA: deterministic final reduction ----
    if (s_last) {
        __threadfence();
        float s = 0.0f;
        for (int r = tid; r < B; r += 256) s += g_partials[r];
        #pragma unroll
        for (int off = 16; off > 0; off >>= 1)
            s += __shfl_down_sync(0xFFFFFFFFu, s, off);
        if (lane == 0) s_rn[wid] = s;
        __syncthreads();
        if (tid == 0) {
            float t = 0.0f;
            #pragma unroll
            for (int w = 0; w < 8; ++w) t += s_rn[w];
            out[0] = t / (float)B;
            g_done = 0;   // reset for next graph replay
        }
    }
}

extern "C" void kernel_launch(void* const* d_in, const int* in_sizes, int n_in,
                              void* d_out, int out_size)
{
    const float* scores = (const float*)d_in[0];
    const int*   relev  = (const int*)  d_in[1];
    const int*   qlen   = (const int*)  d_in[2];
    float*       out    = (float*)      d_out;

    const int B = in_sizes[2];
    const int D = in_sizes[0] / B;   // 128

    ndcg_kernel<<<B, 256>>>(scores, relev, qlen, out, D, B);
}